// round 2
// baseline (speedup 1.0000x reference)
#include <cuda_runtime.h>
#include <cuda_bf16.h>
#include <cstdint>
#include <cstddef>

// RNN-T beam search. B=8, T=128, H=1024, V=4096, K=5 (M = 40 hyps).
// Inputs: 0 tn_output[8,128,1024] 1 E[4096,1024] 2 W_ih[4096,1024]
// 3 W_hh[4096,1024] 4 b_lstm[4096] 5 W_tn[1024,1024] 6 W_pn[1024,1024]
// 7 b_joint[1024] 8 W_out[1024,4096] 9 b_out[4096]
// Output f32 flat: best_preds[8*128], best_lens[8], mean_score, norm[8*5]

#define HH   1024
#define VV   4096
#define BB   8
#define KBM  5
#define MM   40
#define TT   128

// ----------------------------- device state --------------------------------
__device__ float g_tnproj[BB * TT * HH];      // 4 MB
__device__ float g_partial[8 * MM * VV];      // 5.24 MB scratch (max split use)
__device__ float g_h[2][MM * HH];
__device__ float g_c[2][MM * HH];
__device__ float g_hnew[MM * HH];
__device__ float g_cnew[MM * HH];
__device__ float g_joint[MM * HH];
__device__ float g_logits[MM * VV];
__device__ float g_scores[2][MM];
__device__ int   g_tokens[2][MM];
__device__ int   g_lens[2][MM];
__device__ int   g_preds[2][MM * TT];

__device__ __forceinline__ float sigm(float x) { return 1.0f / (1.0f + expf(-x)); }

// ----------------------------- init ----------------------------------------
__global__ void init_state() {
    int idx = blockIdx.x * 256 + threadIdx.x;   // 160*256 = 40960
    if (idx < MM * HH) { g_h[0][idx] = 0.0f; g_c[0][idx] = 0.0f; }
    if (idx < MM) {
        g_scores[0][idx] = (idx % KBM == 0) ? 0.0f : -1e9f;
        g_tokens[0][idx] = 0;
        g_lens[0][idx]   = 0;
    }
    if (idx < MM * TT) g_preds[0][idx] = 0;
}

// ----------------------------- tn_proj GEMM --------------------------------
// C[1024,1024] = A[1024,1024] @ B[1024,1024] (NN)
__global__ __launch_bounds__(256) void tnproj_gemm(const float* __restrict__ A,
                                                   const float* __restrict__ Bm) {
    __shared__ float As[16][65];
    __shared__ float Bs[16][64];
    int tid = threadIdx.x;
    int tx = tid & 15, ty = tid >> 4;
    int m0 = blockIdx.y * 64, n0 = blockIdx.x * 64;
    float acc[4][4];
#pragma unroll
    for (int i = 0; i < 4; i++)
#pragma unroll
        for (int j = 0; j < 4; j++) acc[i][j] = 0.0f;

    for (int kk = 0; kk < 1024; kk += 16) {
        {
            int mm = tid >> 2;
            int kq = (tid & 3) * 4;
            float4 v = *(const float4*)&A[(size_t)(m0 + mm) * 1024 + kk + kq];
            As[kq + 0][mm] = v.x; As[kq + 1][mm] = v.y;
            As[kq + 2][mm] = v.z; As[kq + 3][mm] = v.w;
        }
#pragma unroll
        for (int r = 0; r < 4; r++) {
            int idx = tid + r * 256;
            int k = idx >> 6, n = idx & 63;
            Bs[k][n] = Bm[(size_t)(kk + k) * 1024 + n0 + n];
        }
        __syncthreads();
#pragma unroll
        for (int k = 0; k < 16; k++) {
            float a[4], b[4];
#pragma unroll
            for (int i = 0; i < 4; i++) a[i] = As[k][ty + 16 * i];
#pragma unroll
            for (int j = 0; j < 4; j++) b[j] = Bs[k][tx + 16 * j];
#pragma unroll
            for (int i = 0; i < 4; i++)
#pragma unroll
                for (int j = 0; j < 4; j++) acc[i][j] += a[i] * b[j];
        }
        __syncthreads();
    }
#pragma unroll
    for (int i = 0; i < 4; i++)
#pragma unroll
        for (int j = 0; j < 4; j++)
            g_tnproj[(size_t)(m0 + ty + 16 * i) * 1024 + n0 + tx + 16 * j] = acc[i][j];
}

// ----------------------------- gates GEMM ----------------------------------
// out[m,n] = sum_k A(m,k)*W(n,k); k<1024: A=E[tok], W=W_ih; else A=h, W=W_hh.
// grid (16, 8): 256 output cols per block, K-split of 256 per y-block.
__global__ __launch_bounds__(256) void gemm_gates(const float* __restrict__ Emat,
                                                  const float* __restrict__ W_ih,
                                                  const float* __restrict__ W_hh,
                                                  int cur) {
    __shared__ float As[32][41];
    __shared__ float Bs[32][256];
    __shared__ const float* Arow[MM];
    int tid = threadIdx.x;
    int n0 = blockIdx.x * 256;
    int kbase = blockIdx.y * 256;
    bool embside = (kbase < 1024);
    if (tid < MM) {
        Arow[tid] = embside ? (Emat + (size_t)g_tokens[cur][tid] * HH + kbase)
                            : (g_h[cur] + (size_t)tid * HH + (kbase - 1024));
    }
    const float* Wb = embside ? (W_ih + kbase) : (W_hh + (kbase - 1024));
    const float* wrow = Wb + (size_t)(n0 + tid) * HH;
    __syncthreads();

    float acc[10][4];
#pragma unroll
    for (int i = 0; i < 10; i++) { acc[i][0] = acc[i][1] = acc[i][2] = acc[i][3] = 0.0f; }
    int nn = tid & 63, m0 = (tid >> 6) * 10;

    for (int it = 0; it < 8; ++it) {
        int kl = it * 32;
#pragma unroll
        for (int r = 0; r < 5; r++) {
            int i = tid + r * 256;
            int m = i >> 5, kk = i & 31;
            As[kk][m] = Arow[m][kl + kk];
        }
        {
            const float4* wp = (const float4*)(wrow + kl);
#pragma unroll
            for (int r = 0; r < 8; r++) {
                float4 v = wp[r];
                Bs[r * 4 + 0][tid] = v.x; Bs[r * 4 + 1][tid] = v.y;
                Bs[r * 4 + 2][tid] = v.z; Bs[r * 4 + 3][tid] = v.w;
            }
        }
        __syncthreads();
#pragma unroll 4
        for (int kk = 0; kk < 32; ++kk) {
            float b0 = Bs[kk][nn], b1 = Bs[kk][nn + 64];
            float b2 = Bs[kk][nn + 128], b3 = Bs[kk][nn + 192];
#pragma unroll
            for (int i = 0; i < 10; i++) {
                float a = As[kk][m0 + i];
                acc[i][0] += a * b0; acc[i][1] += a * b1;
                acc[i][2] += a * b2; acc[i][3] += a * b3;
            }
        }
        __syncthreads();
    }
    float* p = g_partial + (size_t)blockIdx.y * MM * VV;
#pragma unroll
    for (int i = 0; i < 10; i++) {
        size_t row = (size_t)(m0 + i) * VV + n0;
        p[row + nn]       = acc[i][0];
        p[row + nn + 64]  = acc[i][1];
        p[row + nn + 128] = acc[i][2];
        p[row + nn + 192] = acc[i][3];
    }
}

// ----------------------------- NN-layout GEMM ------------------------------
// out[m,n] = sum_k A[m,k]*B[k,n], A [40,1024] (ASRC 0=g_hnew, 1=g_joint).
// grid (NTOT/256, SPLITS), k chunk = ITERS*32.
template <int NTOT, int ITERS, int ASRC>
__global__ __launch_bounds__(256) void gemm_nn(const float* __restrict__ Bm) {
    __shared__ float As[32][41];
    __shared__ float Bs[32][256];
    const float* A = (ASRC == 0) ? g_hnew : g_joint;
    int tid = threadIdx.x;
    int n0 = blockIdx.x * 256;
    int kbase = blockIdx.y * (ITERS * 32);

    float acc[10][4];
#pragma unroll
    for (int i = 0; i < 10; i++) { acc[i][0] = acc[i][1] = acc[i][2] = acc[i][3] = 0.0f; }
    int nn = tid & 63, m0 = (tid >> 6) * 10;
    int kt = tid >> 6;
    int n4 = (tid & 63) * 4;

    for (int it = 0; it < ITERS; ++it) {
        int kl = kbase + it * 32;
#pragma unroll
        for (int r = 0; r < 5; r++) {
            int i = tid + r * 256;
            int m = i >> 5, kk = i & 31;
            As[kk][m] = A[(size_t)m * HH + kl + kk];
        }
#pragma unroll
        for (int r = 0; r < 8; r++) {
            int kk = kt + 4 * r;
            float4 v = *(const float4*)&Bm[(size_t)(kl + kk) * NTOT + n0 + n4];
            *(float4*)&Bs[kk][n4] = v;
        }
        __syncthreads();
#pragma unroll 4
        for (int kk = 0; kk < 32; ++kk) {
            float b0 = Bs[kk][nn], b1 = Bs[kk][nn + 64];
            float b2 = Bs[kk][nn + 128], b3 = Bs[kk][nn + 192];
#pragma unroll
            for (int i = 0; i < 10; i++) {
                float a = As[kk][m0 + i];
                acc[i][0] += a * b0; acc[i][1] += a * b1;
                acc[i][2] += a * b2; acc[i][3] += a * b3;
            }
        }
        __syncthreads();
    }
    float* p = g_partial + (size_t)blockIdx.y * MM * NTOT;
#pragma unroll
    for (int i = 0; i < 10; i++) {
        size_t row = (size_t)(m0 + i) * NTOT + n0;
        p[row + nn]       = acc[i][0];
        p[row + nn + 64]  = acc[i][1];
        p[row + nn + 128] = acc[i][2];
        p[row + nn + 192] = acc[i][3];
    }
}

// ----------------------------- LSTM pointwise ------------------------------
// Reduce 8 gate partials + bias, apply LSTM cell. grid 160x256.
__global__ void lstm_pw(const float* __restrict__ b_lstm, int cur) {
    int e = blockIdx.x * 256 + threadIdx.x;    // 40960 = 40*1024
    int m = e >> 10, j = e & 1023;
    float gi = b_lstm[j], gf = b_lstm[1024 + j], gg = b_lstm[2048 + j], go = b_lstm[3072 + j];
#pragma unroll
    for (int s = 0; s < 8; s++) {
        const float* p = g_partial + (size_t)s * MM * VV + (size_t)m * VV;
        gi += p[j]; gf += p[1024 + j]; gg += p[2048 + j]; go += p[3072 + j];
    }
    float c_old = g_c[cur][e];
    float c_new = sigm(gf) * c_old + sigm(gi) * tanhf(gg);
    float h_new = sigm(go) * tanhf(c_new);
    g_cnew[e] = c_new;
    g_hnew[e] = h_new;
}

// ----------------------------- joint reduce --------------------------------
// g_joint = tanh(tn_proj[b,t] + sum_16 partials + b_joint). grid 160x256.
__global__ void joint_reduce(const float* __restrict__ b_joint, int t) {
    int e = blockIdx.x * 256 + threadIdx.x;    // 40960
    int m = e >> 10, j = e & 1023;
    float v = b_joint[j];
#pragma unroll
    for (int s = 0; s < 16; s++) v += g_partial[(size_t)s * MM * HH + e];
    int b = m / KBM;
    v += g_tnproj[((size_t)b * TT + t) * HH + j];
    g_joint[e] = tanhf(v);
}

// ----------------------------- logits reduce -------------------------------
__global__ void logits_reduce(const float* __restrict__ b_out) {
    int e = blockIdx.x * 256 + threadIdx.x;    // 163840 = 40*4096
    int n = e & 4095;
    float v = b_out[n];
#pragma unroll
    for (int s = 0; s < 8; s++) v += g_partial[(size_t)s * MM * VV + e];
    g_logits[e] = v;
}

// ----------------------------- topk + state update -------------------------
// One block per batch. log-softmax per row, top-5 over K*V cands, update state.
__global__ __launch_bounds__(256) void topk_update(int cur) {
    int b = blockIdx.x, tid = threadIdx.x;
    int nxt = cur ^ 1;
    __shared__ float sv[256];
    __shared__ int   si[256];
    __shared__ float s_lse[KBM];
    __shared__ int   ch_idx[KBM];
    __shared__ float ch_val[KBM];
    __shared__ int   s_par[KBM], s_tok[KBM], s_blank[KBM], s_plen[KBM];

    // --- log-sum-exp per beam row ---
    for (int r = 0; r < KBM; r++) {
        const float* row = g_logits + (size_t)(b * KBM + r) * VV;
        float mx = -3e38f;
        for (int v = tid; v < VV; v += 256) mx = fmaxf(mx, row[v]);
        sv[tid] = mx; __syncthreads();
        for (int s2 = 128; s2 > 0; s2 >>= 1) {
            if (tid < s2) sv[tid] = fmaxf(sv[tid], sv[tid + s2]);
            __syncthreads();
        }
        float rowmax = sv[0]; __syncthreads();
        float se = 0.0f;
        for (int v = tid; v < VV; v += 256) se += expf(row[v] - rowmax);
        sv[tid] = se; __syncthreads();
        for (int s2 = 128; s2 > 0; s2 >>= 1) {
            if (tid < s2) sv[tid] += sv[tid + s2];
            __syncthreads();
        }
        if (tid == 0) s_lse[r] = rowmax + logf(sv[0]);
        __syncthreads();
    }

    // --- top-5 (value desc, index asc tie-break, matching lax.top_k) ---
    for (int j = 0; j < KBM; j++) {
        float bv = -3e38f; int bi = 0x7fffffff;
        for (int i = tid; i < KBM * VV; i += 256) {
            bool skip = false;
            for (int q = 0; q < j; q++) if (ch_idx[q] == i) skip = true;
            if (skip) continue;
            int r = i >> 12, v = i & 4095;
            float val = g_scores[cur][b * KBM + r]
                      + g_logits[(size_t)(b * KBM + r) * VV + v] - s_lse[r];
            if (val > bv || (val == bv && i < bi)) { bv = val; bi = i; }
        }
        sv[tid] = bv; si[tid] = bi; __syncthreads();
        for (int s2 = 128; s2 > 0; s2 >>= 1) {
            if (tid < s2) {
                float v2 = sv[tid + s2]; int i2 = si[tid + s2];
                if (v2 > sv[tid] || (v2 == sv[tid] && i2 < si[tid])) {
                    sv[tid] = v2; si[tid] = i2;
                }
            }
            __syncthreads();
        }
        if (tid == 0) { ch_idx[j] = si[0]; ch_val[j] = sv[0]; }
        __syncthreads();
    }

    // --- decode winners, scalar state ---
    if (tid < KBM) {
        int idx = ch_idx[tid];
        int par = idx >> 12, tok = idx & 4095;
        int blk = (tok == 0);
        int p = b * KBM + par;
        int mnew = b * KBM + tid;
        s_par[tid] = par; s_tok[tid] = tok; s_blank[tid] = blk;
        s_plen[tid] = g_lens[cur][p];
        g_scores[nxt][mnew] = ch_val[tid];
        g_lens[nxt][mnew]   = s_plen[tid] + (blk ? 0 : 1);
        g_tokens[nxt][mnew] = blk ? g_tokens[cur][p] : tok;
    }
    __syncthreads();

    // --- gather h/c/preds into next buffers ---
    for (int j = 0; j < KBM; j++) {
        int p = b * KBM + s_par[j], mnew = b * KBM + j;
        bool blk = (s_blank[j] != 0);
        const float* hs = blk ? (g_h[cur] + (size_t)p * HH) : (g_hnew + (size_t)p * HH);
        const float* cs = blk ? (g_c[cur] + (size_t)p * HH) : (g_cnew + (size_t)p * HH);
        for (int i = tid; i < HH; i += 256) {
            g_h[nxt][(size_t)mnew * HH + i] = hs[i];
            g_c[nxt][(size_t)mnew * HH + i] = cs[i];
        }
        for (int i = tid; i < TT; i += 256) {
            int v = g_preds[cur][p * TT + i];
            if (!blk && i == s_plen[j]) v = s_tok[j];
            g_preds[nxt][mnew * TT + i] = v;
        }
    }
}

// ----------------------------- finalize -------------------------------------
__global__ void finalize(float* __restrict__ out) {
    int tid = threadIdx.x;   // 128 threads
    __shared__ float s_norm[MM];
    __shared__ int   s_best[BB];
    if (tid < MM)
        s_norm[tid] = g_scores[0][tid] / ((float)g_lens[0][tid] + 1.0f);
    __syncthreads();
    if (tid < BB) {
        float bv = -3e38f; int bj = 0;
        for (int j = 0; j < KBM; j++) {
            float v = s_norm[tid * KBM + j];
            if (v > bv) { bv = v; bj = j; }
        }
        s_best[tid] = bj;
        out[BB * TT + tid] = (float)g_lens[0][tid * KBM + bj];
    }
    if (tid < MM) out[BB * TT + BB + 1 + tid] = s_norm[tid];
    __syncthreads();
    if (tid == 0) {
        float acc = 0.0f;
        for (int b2 = 0; b2 < BB; b2++) {
            float bv = -3e38f;
            for (int j = 0; j < KBM; j++) bv = fmaxf(bv, s_norm[b2 * KBM + j]);
            acc += expf(bv);
        }
        out[BB * TT + BB] = acc / (float)BB;
    }
    for (int b2 = 0; b2 < BB; b2++) {
        int m = b2 * KBM + s_best[b2];
        for (int i = tid; i < TT; i += 128)
            out[b2 * TT + i] = (float)g_preds[0][m * TT + i];
    }
}

// ----------------------------- launch ---------------------------------------
extern "C" void kernel_launch(void* const* d_in, const int* in_sizes, int n_in,
                              void* d_out, int out_size) {
    const float* tn      = (const float*)d_in[0];
    const float* E       = (const float*)d_in[1];
    const float* W_ih    = (const float*)d_in[2];
    const float* W_hh    = (const float*)d_in[3];
    const float* b_lstm  = (const float*)d_in[4];
    const float* W_tn    = (const float*)d_in[5];
    const float* W_pn    = (const float*)d_in[6];
    const float* b_joint = (const float*)d_in[7];
    const float* W_out   = (const float*)d_in[8];
    const float* b_out   = (const float*)d_in[9];
    float* out = (float*)d_out;

    init_state<<<160, 256>>>();
    tnproj_gemm<<<dim3(16, 16), 256>>>(tn, W_tn);

    for (int t = 0; t < TT; t++) {
        int cur = t & 1;
        gemm_gates<<<dim3(16, 8), 256>>>(E, W_ih, W_hh, cur);
        lstm_pw<<<160, 256>>>(b_lstm, cur);
        gemm_nn<1024, 2, 0><<<dim3(4, 16), 256>>>(W_pn);
        joint_reduce<<<160, 256>>>(b_joint, t);
        gemm_nn<4096, 4, 1><<<dim3(16, 8), 256>>>(W_out);
        logits_reduce<<<640, 256>>>(b_out);
        topk_update<<<8, 256>>>(cur);
    }
    finalize<<<1, 128>>>(out);
}